// round 5
// baseline (speedup 1.0000x reference)
#include <cuda_runtime.h>
#include <cstdint>

#define BATCH   2
#define HIMG    256
#define WIMG    256
#define CH      96
#define C3      288
#define WINSZ   16
#define SEQ     256
#define NHEADS  4
#define HD      24
#define NWIN    512
#define NTOK    131072

typedef unsigned long long ull;

__device__ float g_qkv[(size_t)NTOK * C3];
__device__ float g_o  [(size_t)NTOK * CH];

__device__ __forceinline__ ull pk2(float lo, float hi) {
    ull r; asm("mov.b64 %0, {%1,%2};" : "=l"(r) : "f"(lo), "f"(hi)); return r;
}
__device__ __forceinline__ void upk2(ull v, float& lo, float& hi) {
    asm("mov.b64 {%0,%1}, %2;" : "=f"(lo), "=f"(hi) : "l"(v));
}
__device__ __forceinline__ ull ffma2(ull a, ull b, ull c) {
    ull d; asm("fma.rn.f32x2 %0, %1, %2, %3;" : "=l"(d) : "l"(a), "l"(b), "l"(c));
    return d;
}

// ---------------------------------------------------------------------------
// GEMM: out[m, n0+n] = sum_k A[m,k]*W[k, n0+n] + bias[n0+n]
// M tile 128, N tile 48 (n0 = 48*blockIdx.y). 256 threads, 8x3 micro-tile,
// f32x2 row-pair packing. smem = 66KB -> 3 CTAs/SM (24 warps) for latency
// hiding; 12 FFMA2 vs ~22 issue slots per k keeps loop fma-bound.
// ---------------------------------------------------------------------------
#define AS_LD 128
#define BS_LD 48
#define NT    48

__global__ __launch_bounds__(256, 3)
void gemm_tok96(const float* __restrict__ A, const float* __restrict__ W,
                const float* __restrict__ bias, float* __restrict__ out,
                int wld, int oldd)
{
    extern __shared__ float sm[];
    float* As = sm;                 // [96][128]  As[k*128 + m]
    float* Bs = sm + 96 * AS_LD;    // [96][48]   Bs[k*48 + n]

    const int tid = threadIdx.x;
    const int m0  = blockIdx.x * 128;
    const int n0  = blockIdx.y * NT;

    // A tile, transposed into smem (2 threads per token row)
    {
        int m    = tid >> 1;
        int half = tid & 1;
        const float4* src = (const float4*)(A + (size_t)(m0 + m) * CH + half * 48);
        #pragma unroll
        for (int i = 0; i < 12; i++) {
            float4 v = src[i];
            int k = half * 48 + i * 4;
            As[(k + 0) * AS_LD + m] = v.x;
            As[(k + 1) * AS_LD + m] = v.y;
            As[(k + 2) * AS_LD + m] = v.z;
            As[(k + 3) * AS_LD + m] = v.w;
        }
    }
    // B tile: 96 k-rows x 48 cols = 1152 float4
    for (int idx = tid; idx < 96 * 12; idx += 256) {
        int k  = idx / 12;
        int c4 = idx - k * 12;
        float4 v = *(const float4*)(W + (size_t)k * wld + n0 + c4 * 4);
        float* dst = Bs + k * BS_LD + c4 * 4;
        dst[0] = v.x; dst[1] = v.y; dst[2] = v.z; dst[3] = v.w;
    }
    __syncthreads();

    const int ty = tid >> 4;   // rows ty*8 .. ty*8+7
    const int tx = tid & 15;   // cols tx*3 .. tx*3+2

    ull acc[4][3];
    #pragma unroll
    for (int i = 0; i < 4; i++)
        #pragma unroll
        for (int j = 0; j < 3; j++) acc[i][j] = 0ULL;

    const float* a_base = As + ty * 8;
    const float* b_base = Bs + tx * 3;

    #pragma unroll 6
    for (int k = 0; k < 96; k++) {
        const ulonglong2* ap = (const ulonglong2*)(a_base + k * AS_LD);
        ulonglong2 a01 = ap[0];
        ulonglong2 a23 = ap[1];
        ull a2[4] = { a01.x, a01.y, a23.x, a23.y };

        const float* bp = b_base + k * BS_LD;
        float b0 = bp[0], b1 = bp[1], b2v = bp[2];
        ull bb[3] = { pk2(b0, b0), pk2(b1, b1), pk2(b2v, b2v) };

        #pragma unroll
        for (int j = 0; j < 3; j++)
            #pragma unroll
            for (int i = 0; i < 4; i++) acc[i][j] = ffma2(a2[i], bb[j], acc[i][j]);
    }

    // epilogue: bias + scalar stores (warp covers 48 contiguous cols/row)
    float bvv[3];
    #pragma unroll
    for (int j = 0; j < 3; j++) bvv[j] = __ldg(bias + n0 + tx * 3 + j);

    #pragma unroll
    for (int i = 0; i < 4; i++) {
        size_t r0 = (size_t)(m0 + ty * 8 + 2 * i);
        float* o0 = out + r0 * oldd + n0 + tx * 3;
        float* o1 = out + (r0 + 1) * oldd + n0 + tx * 3;
        #pragma unroll
        for (int j = 0; j < 3; j++) {
            float l, h; upk2(acc[i][j], l, h);
            o0[j] = l + bvv[j];
            o1[j] = h + bvv[j];
        }
    }
}

// ---------------------------------------------------------------------------
// Fused attention + lepe per (window, head). 128 threads, 2 query rows each.
// occ 4 (192KB smem/SM). QK dot uses split accumulators (chain 6 not 12).
// ---------------------------------------------------------------------------
__global__ __launch_bounds__(128, 4)
void attn_lepe(const float* __restrict__ qkv, const float* __restrict__ pe_w,
               const float* __restrict__ pe_b, float* __restrict__ og)
{
    extern __shared__ float sm[];
    float* ks = sm;            // [256][24]
    float* vs = sm + SEQ * HD; // [256][24]

    const int tid = threadIdx.x;
    const int n   = blockIdx.x;
    const int h   = blockIdx.y;
    const int b   = n >> 8;
    const int wr  = (n >> 4) & 15;
    const int wc  = n & 15;
    const int rowbase = wr * 16;
    const int colbase = wc * 16;

    auto tok = [&](int s) -> int {
        int r = s >> 4, c = s & 15;
        return b * 65536 + (rowbase + r) * 256 + (colbase + c);
    };

    // stage Q through smem (coalesced), pull own rows to regs
    for (int i = tid; i < SEQ * 6; i += 128) {
        int s = i / 6, qd = i - s * 6;
        ((float4*)ks)[i] = *(const float4*)(qkv + (size_t)tok(s) * C3 + h * 72 + qd * 4);
    }
    __syncthreads();
    ull q2[2][12];
    {
        const ull* qa = (const ull*)(ks + tid * HD);
        const ull* qb = (const ull*)(ks + (tid + 128) * HD);
        #pragma unroll
        for (int i = 0; i < 12; i++) { q2[0][i] = qa[i]; q2[1][i] = qb[i]; }
    }
    __syncthreads();

    // cooperative coalesced K/V loads
    for (int i = tid; i < SEQ * 6; i += 128) {
        int s = i / 6, qd = i - s * 6;
        size_t base = (size_t)tok(s) * C3 + h * 72;
        ((float4*)ks)[i] = *(const float4*)(qkv + base + 24 + qd * 4);
        ((float4*)vs)[i] = *(const float4*)(qkv + base + 48 + qd * 4);
    }
    __syncthreads();

    const float scale = 0.20412414523193154f; // 1/sqrt(24)

    ull acc[2][12];
    #pragma unroll
    for (int i = 0; i < 12; i++) { acc[0][i] = 0ULL; acc[1][i] = 0ULL; }
    float l0 = 0.f, l1 = 0.f;

    const ulonglong2* krow = (const ulonglong2*)ks;
    const ulonglong2* vrow = (const ulonglong2*)vs;

    #pragma unroll 2
    for (int j = 0; j < SEQ; j++) {
        const ulonglong2* k4 = krow + j * 6;
        ull d0a = 0ULL, d0b = 0ULL, d1a = 0ULL, d1b = 0ULL;
        #pragma unroll
        for (int i = 0; i < 6; i++) {
            ulonglong2 kk = k4[i];
            d0a = ffma2(q2[0][2 * i],     kk.x, d0a);
            d1a = ffma2(q2[1][2 * i],     kk.x, d1a);
            d0b = ffma2(q2[0][2 * i + 1], kk.y, d0b);
            d1b = ffma2(q2[1][2 * i + 1], kk.y, d1b);
        }
        float a, bb, c, d;
        upk2(d0a, a, bb); upk2(d0b, c, d); float s0 = (a + bb + c + d) * scale;
        upk2(d1a, a, bb); upk2(d1b, c, d); float s1 = (a + bb + c + d) * scale;
        float p0 = __expf(s0), p1 = __expf(s1);
        l0 += p0; l1 += p1;
        ull p02 = pk2(p0, p0), p12 = pk2(p1, p1);
        const ulonglong2* v4 = vrow + j * 6;
        #pragma unroll
        for (int i = 0; i < 6; i++) {
            ulonglong2 vv = v4[i];
            acc[0][2 * i]     = ffma2(p02, vv.x, acc[0][2 * i]);
            acc[1][2 * i]     = ffma2(p12, vv.x, acc[1][2 * i]);
            acc[0][2 * i + 1] = ffma2(p02, vv.y, acc[0][2 * i + 1]);
            acc[1][2 * i + 1] = ffma2(p12, vv.y, acc[1][2 * i + 1]);
        }
    }

    // normalize, add lepe (3x3 depthwise on V image), store
    #pragma unroll
    for (int rr = 0; rr < 2; rr++) {
        int s = tid + rr * 128;
        float inv = 1.0f / (rr ? l1 : l0);
        float o[24];
        #pragma unroll
        for (int i = 0; i < 12; i++) {
            float lo, hi; upk2(acc[rr][i], lo, hi);
            o[2 * i]     = lo * inv;
            o[2 * i + 1] = hi * inv;
        }
        int r = s >> 4, c = s & 15;
        #pragma unroll
        for (int ky = -1; ky <= 1; ky++) {
            int r2 = r + ky;
            if (r2 < 0 || r2 > 15) continue;
            #pragma unroll
            for (int kx = -1; kx <= 1; kx++) {
                int c2 = c + kx;
                if (c2 < 0 || c2 > 15) continue;
                const float* vr = vs + (r2 * 16 + c2) * HD;
                const float* wrow = pe_w + ((ky + 1) * 3 + (kx + 1)) * CH + h * HD;
                #pragma unroll
                for (int d = 0; d < 24; d++) o[d] += vr[d] * __ldg(wrow + d);
            }
        }
        #pragma unroll
        for (int d = 0; d < 24; d++) o[d] += __ldg(pe_b + h * HD + d);

        float4* dst = (float4*)(og + (size_t)tok(s) * CH + h * HD);
        #pragma unroll
        for (int i = 0; i < 6; i++)
            dst[i] = make_float4(o[4 * i], o[4 * i + 1], o[4 * i + 2], o[4 * i + 3]);
    }
}

// ---------------------------------------------------------------------------
extern "C" void kernel_launch(void* const* d_in, const int* in_sizes, int n_in,
                              void* d_out, int out_size)
{
    const float* x     = (const float*)d_in[0];
    const float* qkv_w = (const float*)d_in[1];
    const float* qkv_b = (const float*)d_in[2];
    const float* pe_w  = (const float*)d_in[3];
    const float* pe_b  = (const float*)d_in[4];
    const float* out_w = (const float*)d_in[5];
    const float* out_b = (const float*)d_in[6];
    float* out = (float*)d_out;

    float* qkv_ptr = nullptr;
    float* o_ptr   = nullptr;
    cudaGetSymbolAddress((void**)&qkv_ptr, g_qkv);
    cudaGetSymbolAddress((void**)&o_ptr,   g_o);

    const int gemm_smem = (96 * AS_LD + 96 * BS_LD) * (int)sizeof(float); // 67584
    const int attn_smem = 2 * SEQ * HD * (int)sizeof(float);              // 49152
    cudaFuncSetAttribute(gemm_tok96, cudaFuncAttributeMaxDynamicSharedMemorySize, gemm_smem);
    cudaFuncSetAttribute(attn_lepe,  cudaFuncAttributeMaxDynamicSharedMemorySize, attn_smem);

    // 1) QKV projection: 6 N-tiles of 48 via blockIdx.y
    gemm_tok96<<<dim3(NTOK / 128, 6), 256, gemm_smem>>>(x, qkv_w, qkv_b, qkv_ptr, C3, C3);

    // 2) Fused windowed attention + lepe
    attn_lepe<<<dim3(NWIN, NHEADS), 128, attn_smem>>>(qkv_ptr, pe_w, pe_b, o_ptr);

    // 3) Output projection: 2 N-tiles of 48
    gemm_tok96<<<dim3(NTOK / 128, 2), 256, gemm_smem>>>(o_ptr, out_w, out_b, out, CH, CH);
}